// round 15
// baseline (speedup 1.0000x reference)
#include <cuda_runtime.h>
#include <cuda_bf16.h>

#define N_NODES 100000
#define N_EDGES 3200000
#define SIGMA 0.05f
#define EPT 4  // edges per thread (R13's proven occupancy point)

// Scratch accumulator: (sum_x, sum_y, count, unused) per node.
__device__ float4 g_acc[N_NODES];
// Packed node record: {pos.x, pos.y, cell_type (bits), pad}. One 16B gather
// delivers pos+ct in a single 32B L2 sector access.
__device__ float4 g_node[N_NODES];

__device__ __forceinline__ float fast_ex2(float x) {
    float r; asm("ex2.approx.f32 %0, %1;" : "=f"(r) : "f"(x)); return r;
}
__device__ __forceinline__ float fast_lg2(float x) {
    float r; asm("lg2.approx.f32 %0, %1;" : "=f"(r) : "f"(x)); return r;
}
__device__ __forceinline__ float fast_tanh(float x) {
    float r; asm("tanh.approx.f32 %0, %1;" : "=f"(r) : "f"(x)); return r;
}

// One vector reduction per edge: RED.ADD.F32.V4 via the CUDA float4 atomicAdd
// overload (CUDA 12.8+, sm_90+). This exact path passed in R8/R13/R14.
__device__ __forceinline__ void acc_edge(float4* addr, float x, float y, float cnt) {
#if defined(__CUDA_ARCH__) && (__CUDA_ARCH__ >= 900) && (CUDART_VERSION >= 12080)
    atomicAdd(addr, make_float4(x, y, cnt, 0.0f));
#else
    float* f = (float*)addr;
    atomicAdd(f + 0, x);
    atomicAdd(f + 1, y);
    atomicAdd(f + 2, cnt);
#endif
}

// Fused zero + node-record prep.
__global__ void init_kernel(const float2* __restrict__ pos,
                            const int* __restrict__ cell_type) {
    int i = blockIdx.x * blockDim.x + threadIdx.x;
    if (i < N_NODES) {
        g_acc[i] = make_float4(0.f, 0.f, 0.f, 0.f);
        float2 xy = pos[i];
        g_node[i] = make_float4(xy.x, xy.y, __int_as_float(cell_type[i]), 0.0f);
    }
}

__global__ void __launch_bounds__(256) edge_kernel(
    const float4* __restrict__ p,          // [N_TYPES, 4]
    const int*    __restrict__ edge_index, // [2, N_EDGES]: row0 = dst, row1 = src
    const int*    __restrict__ func_type)  // [N_TYPES]
{
    int t = blockIdx.x * blockDim.x + threadIdx.x;
    int e0 = t * EPT;
    if (e0 >= N_EDGES) return;

    // Coalesced 16B loads of 4 dst and 4 src indices.
    int4 d4 = __ldg((const int4*)&edge_index[e0]);
    int4 s4 = __ldg((const int4*)&edge_index[N_EDGES + e0]);
    int dst[EPT] = {d4.x, d4.y, d4.z, d4.w};
    int src[EPT] = {s4.x, s4.y, s4.z, s4.w};

    // Batch-issue all 8 node-record gathers (each = one 32B L2 sector; the
    // dst record carries cell_type for free).
    float4 nd[EPT];   // dst record: pos + ct
    float4 ns[EPT];   // src record: pos
    #pragma unroll
    for (int k = 0; k < EPT; k++) {
        nd[k] = g_node[dst[k]];
        ns[k] = g_node[src[k]];
    }

    const float inv_2s2 = 1.0f / (2.0f * SIGMA * SIGMA);   // 200
    const float LOG2E = 1.4426950408889634f;
    const float c = -inv_2s2 * LOG2E;

    // Fully branchless body: no BSSY/BSYNC (33-56 cyc per divergent region,
    // ~2 regions per warp-iteration with random types). Mixed-type warps
    // executed both MUFU paths under divergence anyway, so computing both
    // unconditionally adds no MUFU throughput cost. Validity goes into the
    // count lane of the vector RED (invalid edges: dx=dy=0 exactly).
    #pragma unroll
    for (int k = 0; k < EPT; k++) {
        bool valid = (src[k] != dst[k]);

        float dx = ns[k].x - nd[k].x;
        float dy = ns[k].y - nd[k].y;
        float d2 = dx * dx + dy * dy;
        d2 = valid ? d2 : 1.0f;          // reference's NaN guard

        int ct = __float_as_int(nd[k].z);
        float4 pp = __ldg(&p[ct]);       // 4 entries: L1-hot
        int ft = __ldg(&func_type[ct]);

        // f1 = p0*exp(-d2^p1*inv) - p2*exp(-d2^p3*inv)
        float l  = fast_lg2(d2);
        float t1 = fast_ex2(pp.y * l);
        float t2 = fast_ex2(pp.w * l);
        float f1 = pp.x * fast_ex2(t1 * c) - pp.z * fast_ex2(t2 * c);

        // f2 = p0*tanh((dist-p1)*p2)/dist
        float rdist = rsqrtf(d2);
        float dist  = d2 * rdist;
        float f2 = pp.x * fast_tanh((dist - pp.y) * pp.z) * rdist;

        float coef = (ft & 1) ? f2 : f1;
        float vf   = valid ? 1.0f : 0.0f;

        acc_edge(&g_acc[dst[k]], coef * dx, coef * dy, vf);
    }
}

__global__ void finalize_kernel(float2* __restrict__ out) {
    int i = blockIdx.x * blockDim.x + threadIdx.x;
    if (i < N_NODES) {
        float4 a = g_acc[i];
        float inv = 1.0f / fmaxf(a.z, 1.0f);
        out[i] = make_float2(a.x * inv, a.y * inv);
    }
}

extern "C" void kernel_launch(void* const* d_in, const int* in_sizes, int n_in,
                              void* d_out, int out_size) {
    const float2* pos        = (const float2*)d_in[0];
    const float4* p          = (const float4*)d_in[1];
    const int*    cell_type  = (const int*)d_in[2];
    const int*    edge_index = (const int*)d_in[3];
    const int*    func_type  = (const int*)d_in[4];
    float2* out = (float2*)d_out;

    (void)in_sizes; (void)n_in; (void)out_size;

    init_kernel<<<(N_NODES + 255) / 256, 256>>>(pos, cell_type);
    edge_kernel<<<(N_EDGES / EPT + 255) / 256, 256>>>(p, edge_index, func_type);
    finalize_kernel<<<(N_NODES + 255) / 256, 256>>>(out);
}

// round 16
// speedup vs baseline: 1.5717x; 1.5717x over previous
#include <cuda_runtime.h>
#include <cuda_bf16.h>

#define N_NODES 100000
#define N_EDGES 3200000
#define SIGMA 0.05f
#define EPT 2  // edges per thread: ~40 regs -> 6 blocks/SM (48 warps) vs 4 blocks at EPT=4

// Scratch accumulator: (sum_x, sum_y, count, unused) per node.
__device__ float4 g_acc[N_NODES];
// Packed node record: {pos.x, pos.y, cell_type (bits), pad}. One 16B gather
// delivers pos+ct in a single 32B L2 sector access.
__device__ float4 g_node[N_NODES];

__device__ __forceinline__ float fast_ex2(float x) {
    float r; asm("ex2.approx.f32 %0, %1;" : "=f"(r) : "f"(x)); return r;
}
__device__ __forceinline__ float fast_lg2(float x) {
    float r; asm("lg2.approx.f32 %0, %1;" : "=f"(r) : "f"(x)); return r;
}
__device__ __forceinline__ float fast_tanh(float x) {
    float r; asm("tanh.approx.f32 %0, %1;" : "=f"(r) : "f"(x)); return r;
}

// One vector reduction per edge: RED.ADD.F32.V4 via the CUDA float4 atomicAdd
// overload (CUDA 12.8+, sm_90+). This exact path passed in R8/R13/R14/R15.
__device__ __forceinline__ void acc_edge(float4* addr, float x, float y) {
#if defined(__CUDA_ARCH__) && (__CUDA_ARCH__ >= 900) && (CUDART_VERSION >= 12080)
    atomicAdd(addr, make_float4(x, y, 1.0f, 0.0f));
#else
    float* f = (float*)addr;
    atomicAdd(f + 0, x);
    atomicAdd(f + 1, y);
    atomicAdd(f + 2, 1.0f);
#endif
}

// Fused zero + node-record prep.
__global__ void init_kernel(const float2* __restrict__ pos,
                            const int* __restrict__ cell_type) {
    int i = blockIdx.x * blockDim.x + threadIdx.x;
    if (i < N_NODES) {
        g_acc[i] = make_float4(0.f, 0.f, 0.f, 0.f);
        float2 xy = pos[i];
        g_node[i] = make_float4(xy.x, xy.y, __int_as_float(cell_type[i]), 0.0f);
    }
}

__global__ void __launch_bounds__(256) edge_kernel(
    const float4* __restrict__ p,          // [N_TYPES, 4]
    const int*    __restrict__ edge_index, // [2, N_EDGES]: row0 = dst, row1 = src
    const int*    __restrict__ func_type)  // [N_TYPES]
{
    int t = blockIdx.x * blockDim.x + threadIdx.x;
    int e0 = t * EPT;
    if (e0 >= N_EDGES) return;

    // Coalesced 8B loads of 2 dst and 2 src indices.
    int2 d2i = __ldg((const int2*)&edge_index[e0]);
    int2 s2i = __ldg((const int2*)&edge_index[N_EDGES + e0]);
    int dst[EPT] = {d2i.x, d2i.y};
    int src[EPT] = {s2i.x, s2i.y};

    // Batch-issue all 4 node-record gathers (each = one 32B L2 sector; the
    // dst record carries cell_type for free).
    float4 nd[EPT];   // dst record: pos + ct
    float4 ns[EPT];   // src record: pos
    #pragma unroll
    for (int k = 0; k < EPT; k++) {
        nd[k] = g_node[dst[k]];
        ns[k] = g_node[src[k]];
    }

    const float inv_2s2 = 1.0f / (2.0f * SIGMA * SIGMA);   // 200
    const float LOG2E = 1.4426950408889634f;
    const float c = -inv_2s2 * LOG2E;

    #pragma unroll
    for (int k = 0; k < EPT; k++) {
        if (src[k] == dst[k]) continue;  // invalid edge: no contribution

        float dx = ns[k].x - nd[k].x;
        float dy = ns[k].y - nd[k].y;
        float d2 = dx * dx + dy * dy;

        int ct = __float_as_int(nd[k].z);
        float4 pp = __ldg(&p[ct]);       // 4 entries: L1-hot
        int ft = __ldg(&func_type[ct]);

        float coef;
        if ((ft & 1) == 1) {
            // f2 = p0 * tanh((dist - p1) * p2) / dist
            float rdist = rsqrtf(d2);
            float dist  = d2 * rdist;
            float tv = fast_tanh((dist - pp.y) * pp.z);
            coef = pp.x * tv * rdist;
        } else {
            // f1 = p0 * exp(-d2^p1 * inv) - p2 * exp(-d2^p3 * inv)
            float l = fast_lg2(d2);
            float t1 = fast_ex2(pp.y * l);   // d2^p1
            float t2 = fast_ex2(pp.w * l);   // d2^p3
            coef = pp.x * fast_ex2(t1 * c) - pp.z * fast_ex2(t2 * c);
        }

        acc_edge(&g_acc[dst[k]], coef * dx, coef * dy);
    }
}

__global__ void finalize_kernel(float2* __restrict__ out) {
    int i = blockIdx.x * blockDim.x + threadIdx.x;
    if (i < N_NODES) {
        float4 a = g_acc[i];
        float inv = 1.0f / fmaxf(a.z, 1.0f);
        out[i] = make_float2(a.x * inv, a.y * inv);
    }
}

extern "C" void kernel_launch(void* const* d_in, const int* in_sizes, int n_in,
                              void* d_out, int out_size) {
    const float2* pos        = (const float2*)d_in[0];
    const float4* p          = (const float4*)d_in[1];
    const int*    cell_type  = (const int*)d_in[2];
    const int*    edge_index = (const int*)d_in[3];
    const int*    func_type  = (const int*)d_in[4];
    float2* out = (float2*)d_out;

    (void)in_sizes; (void)n_in; (void)out_size;

    init_kernel<<<(N_NODES + 255) / 256, 256>>>(pos, cell_type);
    edge_kernel<<<(N_EDGES / EPT + 255) / 256, 256>>>(p, edge_index, func_type);
    finalize_kernel<<<(N_NODES + 255) / 256, 256>>>(out);
}